// round 1
// baseline (speedup 1.0000x reference)
#include <cuda_runtime.h>

#define Bb 4
#define Ss 2048
#define Hh 16
#define Dd 64
#define BH (Bb*Hh)
#define TILE 64
#define NQT (Ss/TILE)   // 32
#define PAD 68

// reciprocal of softmax denominator per (b,h,row)
__device__ float g_linv[BH*Ss];

__global__ __launch_bounds__(256) void attn_pass1(
    const float* __restrict__ q,
    const float* __restrict__ k,
    const float* __restrict__ v,
    float* __restrict__ out,
    float* __restrict__ attn)
{
    extern __shared__ float sm[];
    float* qs = sm;                 // transposed: qs[kk*PAD + m], scaled by 1/8
    float* kp = sm + 64*PAD;        // K transposed kp[kk*PAD + n]  (later reused as P[r*PAD + n])
    float* vs = sm + 2*64*PAD;      // vs[n*PAD + d]

    const int t  = threadIdx.x;
    const int ty = t >> 4;          // 0..15 -> rows 4*ty..4*ty+3
    const int tx = t & 15;          // 0..15 -> cols 4*tx..4*tx+3
    const int bh = blockIdx.y;
    const int b  = bh >> 4;
    const int h  = bh & 15;
    const int qt = (NQT - 1) - blockIdx.x;   // big tiles scheduled first
    const int qr0 = qt * TILE;

    const float* qb = q + (size_t)b*Ss*Hh*Dd + (size_t)h*Dd;
    const float* kb = k + (size_t)b*Ss*Hh*Dd + (size_t)h*Dd;
    const float* vb = v + (size_t)b*Ss*Hh*Dd + (size_t)h*Dd;
    float* attnb = attn + (size_t)bh*Ss*Ss;

    // ---- load Q tile (transposed + scaled 1/temperature) ----
    {
        const int n  = t & 63;
        const int d0 = (t >> 6) * 16;
        const float* src = qb + (size_t)(qr0 + n)*(Hh*Dd) + d0;
        #pragma unroll
        for (int c4 = 0; c4 < 4; c4++) {
            float4 val = *(const float4*)(src + c4*4);
            int d = d0 + c4*4;
            qs[(d+0)*PAD + n] = val.x * 0.125f;
            qs[(d+1)*PAD + n] = val.y * 0.125f;
            qs[(d+2)*PAD + n] = val.z * 0.125f;
            qs[(d+3)*PAD + n] = val.w * 0.125f;
        }
    }
    __syncthreads();

    float acc_o[4][4];
    #pragma unroll
    for (int i = 0; i < 4; i++)
        #pragma unroll
        for (int j = 0; j < 4; j++) acc_o[i][j] = 0.f;
    float lsum[4] = {0.f, 0.f, 0.f, 0.f};

    for (int kt = 0; kt <= qt; kt++) {
        const int kc0 = kt * TILE;
        // ---- load K (transposed) and V tiles ----
        {
            const int n  = t & 63;
            const int d0 = (t >> 6) * 16;
            const float* ksrc = kb + (size_t)(kc0 + n)*(Hh*Dd) + d0;
            #pragma unroll
            for (int c4 = 0; c4 < 4; c4++) {
                float4 val = *(const float4*)(ksrc + c4*4);
                int d = d0 + c4*4;
                kp[(d+0)*PAD + n] = val.x;
                kp[(d+1)*PAD + n] = val.y;
                kp[(d+2)*PAD + n] = val.z;
                kp[(d+3)*PAD + n] = val.w;
            }
            const int n2  = t >> 2;
            const int d20 = (t & 3) * 16;
            const float* vsrc = vb + (size_t)(kc0 + n2)*(Hh*Dd) + d20;
            #pragma unroll
            for (int c4 = 0; c4 < 4; c4++) {
                float4 val = *(const float4*)(vsrc + c4*4);
                *(float4*)&vs[n2*PAD + d20 + c4*4] = val;
            }
        }
        __syncthreads();

        // ---- S = Q K^T ----
        float s_[4][4];
        #pragma unroll
        for (int i = 0; i < 4; i++)
            #pragma unroll
            for (int j = 0; j < 4; j++) s_[i][j] = 0.f;

        #pragma unroll 4
        for (int kk = 0; kk < 64; kk++) {
            float4 av = *(const float4*)(qs + kk*PAD + 4*ty);
            float4 bv = *(const float4*)(kp + kk*PAD + 4*tx);
            float a[4] = {av.x, av.y, av.z, av.w};
            float bb[4] = {bv.x, bv.y, bv.z, bv.w};
            #pragma unroll
            for (int i = 0; i < 4; i++)
                #pragma unroll
                for (int j = 0; j < 4; j++)
                    s_[i][j] += a[i] * bb[j];
        }

        // ---- P = exp(S) with causal mask; accumulate row sums ----
        float p[4][4];
        #pragma unroll
        for (int i = 0; i < 4; i++) {
            const int rg = qr0 + 4*ty + i;
            #pragma unroll
            for (int j = 0; j < 4; j++) {
                const int cg = kc0 + 4*tx + j;
                float e = (cg <= rg) ? __expf(s_[i][j]) : 0.f;
                p[i][j] = e;
                lsum[i] += e;
            }
        }

        __syncthreads();   // everyone done reading kp (K) before reuse as P

        // ---- store P to smem (reuse kp) and to gmem attn (unnormalized) ----
        #pragma unroll
        for (int i = 0; i < 4; i++) {
            float4 pv = make_float4(p[i][0], p[i][1], p[i][2], p[i][3]);
            *(float4*)&kp[(4*ty + i)*PAD + 4*tx] = pv;
            *(float4*)&attnb[(size_t)(qr0 + 4*ty + i)*Ss + kc0 + 4*tx] = pv;
        }
        __syncthreads();

        // ---- O += P V ----
        #pragma unroll 4
        for (int n = 0; n < 64; n++) {
            float4 vv = *(const float4*)&vs[n*PAD + 4*tx];
            #pragma unroll
            for (int i = 0; i < 4; i++) {
                float pv = kp[(4*ty + i)*PAD + n];
                acc_o[i][0] += pv * vv.x;
                acc_o[i][1] += pv * vv.y;
                acc_o[i][2] += pv * vv.z;
                acc_o[i][3] += pv * vv.w;
            }
        }
        __syncthreads();   // before next tile overwrites kp/vs
    }

    // ---- zero-fill the masked (strictly upper) region of attn ----
    {
        const int zc0 = (qt + 1) * TILE;
        const float4 z = make_float4(0.f, 0.f, 0.f, 0.f);
        #pragma unroll
        for (int i = 0; i < 4; i++) {
            const size_t rowbase = (size_t)(qr0 + 4*ty + i) * Ss;
            for (int c = zc0 + 4*tx; c < Ss; c += 64)
                *(float4*)&attnb[rowbase + c] = z;
        }
    }

    // ---- reduce row sums across the 16 tx lanes (butterfly within 16-group) ----
    float inv[4];
    #pragma unroll
    for (int i = 0; i < 4; i++) {
        float s = lsum[i];
        s += __shfl_xor_sync(0xffffffffu, s, 1);
        s += __shfl_xor_sync(0xffffffffu, s, 2);
        s += __shfl_xor_sync(0xffffffffu, s, 4);
        s += __shfl_xor_sync(0xffffffffu, s, 8);
        inv[i] = 1.0f / s;
    }
    if (tx == 0) {
        #pragma unroll
        for (int i = 0; i < 4; i++)
            g_linv[bh*Ss + qr0 + 4*ty + i] = inv[i];
    }

    // ---- write normalized O ----
    #pragma unroll
    for (int i = 0; i < 4; i++) {
        const int rg = qr0 + 4*ty + i;
        float4 o = make_float4(acc_o[i][0]*inv[i], acc_o[i][1]*inv[i],
                               acc_o[i][2]*inv[i], acc_o[i][3]*inv[i]);
        *(float4*)&out[(size_t)b*Ss*Hh*Dd + (size_t)rg*(Hh*Dd) + h*Dd + 4*tx] = o;
    }
}

// Normalize only the causal (nonzero) prefix of each attn row.
__global__ __launch_bounds__(256) void attn_norm(float* __restrict__ attn)
{
    const int row = blockIdx.x;           // 0 .. BH*S-1
    const int jl  = row & (Ss - 1);       // row index within sequence
    const float inv = g_linv[row];
    const int n4 = (jl + 4) >> 2;         // ceil((jl+1)/4) float4s to touch
    float4* p = (float4*)(attn + (size_t)row * Ss);
    for (int c = threadIdx.x; c < n4; c += blockDim.x) {
        float4 t = p[c];
        t.x *= inv; t.y *= inv; t.z *= inv; t.w *= inv;
        p[c] = t;
    }
}

extern "C" void kernel_launch(void* const* d_in, const int* in_sizes, int n_in,
                              void* d_out, int out_size)
{
    const float* q = (const float*)d_in[0];
    const float* k = (const float*)d_in[1];
    const float* v = (const float*)d_in[2];
    // d_in[3] = causal mask, deterministic triu -> handled analytically

    float* out  = (float*)d_out;
    float* attn = (float*)d_out + (size_t)Bb*Ss*Hh*Dd;

    const int smem = 3 * 64 * PAD * (int)sizeof(float);   // 52224 B
    cudaFuncSetAttribute(attn_pass1, cudaFuncAttributeMaxDynamicSharedMemorySize, smem);

    dim3 grid(NQT, BH);
    attn_pass1<<<grid, 256, smem>>>(q, k, v, out, attn);
    attn_norm<<<BH*Ss, 256>>>(attn);
}

// round 3
// speedup vs baseline: 2.1204x; 2.1204x over previous
#include <cuda_runtime.h>
#include <cstdint>

#define Bb 4
#define Ss 2048
#define Hh 16
#define BHh 64
#define Dd 64
#define TM 128
#define TN 128
#define NQT 16   // Ss / TM

// Arch-specific feature gate: tcgen05 only exists on sm_10Xa targets.
#if defined(__CUDA_ARCH__) && (defined(__CUDA_ARCH_FEAT_SM103_ALL) || \
                               defined(__CUDA_ARCH_FEAT_SM100_ALL) || \
                               defined(__CUDA_ARCH_FEAT_SM101_ALL))
#define USE_TC 1
#else
#define USE_TC 0
#endif

// ---------------- shared constants ----------------
// tcgen05-path SMEM byte offsets
#define SMEM_TMEMPTR 0
#define SMEM_MBAR_S 64
#define SMEM_MBAR_PV 72
#define SMEM_RS 1024       /* 2 x 128 floats */
#define OFF_QHI 2048
#define OFF_QLO 34816
#define OFF_KHI 67584
#define OFF_KLO 100352
#define OFF_VT  133120
#define OFF_PS  165888
#define SMEM_BYTES 231424

// idesc: c_format=F32(1)<<4, a_format=TF32(2)<<7, b_format=TF32(2)<<10,
// n_dim=(N>>3)<<17, m_dim=(M>>4)<<24
#define IDESC_S ((1u<<4)|(2u<<7)|(2u<<10)|((TN/8)<<17)|((TM/16)<<24))
#define IDESC_O ((1u<<4)|(2u<<7)|(2u<<10)|((64/8)<<17)|((TM/16)<<24))

// K-major SW128 smem descriptor base (layout=2, version=1, SBO=64, LBO=1)
#define SMEM_DESC_BASE ((uint64_t(2)<<61)|(uint64_t(1)<<46)|(uint64_t(64)<<32)|(uint64_t(1)<<16))
#define MAKE_DESC(a) (SMEM_DESC_BASE | ((uint64_t)((a) >> 4) & 0x3FFF))

__device__ float g_linv[BHh * Ss];

// ---------- arch-agnostic helpers ----------
__device__ __forceinline__ uint32_t smem_u32(const void* p) {
    uint32_t a;
    asm("{ .reg .u64 t; cvta.to.shared.u64 t, %1; cvt.u32.u64 %0, t; }" : "=r"(a) : "l"(p));
    return a;
}
__device__ __forceinline__ uint32_t sw128(uint32_t x) { return x ^ ((x >> 3) & 0x70); }
// 128-row tiles (Q, K, P): blocked SW128 atoms (8 rows x 32 f32), 16 atom-rows
__device__ __forceinline__ uint32_t off128(int r, int c) {
    return sw128((uint32_t)((((r >> 3) + (c >> 5) * 16) << 10) + ((r & 7) << 7) + ((c & 31) << 2)));
}
// 64-row tiles (V^T): 8 atom-rows
__device__ __forceinline__ uint32_t off64(int r, int c) {
    return sw128((uint32_t)((((r >> 3) + (c >> 5) * 8) << 10) + ((r & 7) << 7) + ((c & 31) << 2)));
}

#if USE_TC
// ---------- tcgen05 PTX helpers ----------
__device__ __forceinline__ uint32_t elect_one() {
    uint32_t pred;
    asm volatile("{\n\t.reg .pred p;\n\telect.sync _|p, 0xFFFFFFFF;\n\tselp.b32 %0, 1, 0, p;\n\t}"
                 : "=r"(pred));
    return pred;
}
#define MBAR_INIT(addr, cnt) \
    asm volatile("mbarrier.init.shared.b64 [%0], %1;" :: "r"(addr), "r"(cnt) : "memory")
#define MBAR_INVAL(addr) \
    asm volatile("mbarrier.inval.shared.b64 [%0];" :: "r"(addr) : "memory")
#define MBAR_WAIT(addr, parity) do { \
    uint32_t _m = (uint32_t)(addr); uint32_t _p = (uint32_t)(parity); uint32_t _d; \
    asm volatile("{\n\t.reg .pred p;\n\t" \
        "mbarrier.try_wait.parity.acquire.cta.shared::cta.b64 p, [%1], %2;\n\t" \
        "selp.b32 %0, 1, 0, p;\n\t}" : "=r"(_d) : "r"(_m), "r"(_p) : "memory"); \
    if (!_d) { \
        asm volatile("{\n\t.reg .pred P1;\n\t" \
            "WL_%=:\n\t" \
            "mbarrier.try_wait.parity.acquire.cta.shared::cta.b64 P1, [%0], %1, 0x989680;\n\t" \
            "@P1 bra.uni WD_%=;\n\t" \
            "bra.uni WL_%=;\n\t" \
            "WD_%=:\n\t}" :: "r"(_m), "r"(_p) : "memory"); \
    } \
} while (0)

#define TC_ALLOC(smem_addr, ncols) \
    asm volatile("tcgen05.alloc.cta_group::1.sync.aligned.shared::cta.b32 [%0], %1;" \
                 :: "r"((uint32_t)(smem_addr)), "r"((uint32_t)(ncols)) : "memory")
#define TC_DEALLOC(tmem, ncols) \
    asm volatile("tcgen05.dealloc.cta_group::1.sync.aligned.b32 %0, %1;" \
                 :: "r"(tmem), "r"((uint32_t)(ncols)))
#define TC_RELINQ() \
    asm volatile("tcgen05.relinquish_alloc_permit.cta_group::1.sync.aligned;")
#define TC_COMMIT(mbar) \
    asm volatile("tcgen05.commit.cta_group::1.mbarrier::arrive::one.shared::cluster.b64 [%0];" \
                 :: "r"((uint32_t)(mbar)) : "memory")
#define TC_FENCE_BEFORE() asm volatile("tcgen05.fence::before_thread_sync;" ::: "memory")
#define TC_FENCE_AFTER()  asm volatile("tcgen05.fence::after_thread_sync;" ::: "memory")
#define TC_WAIT_LD() asm volatile("tcgen05.wait::ld.sync.aligned;" ::: "memory")
#define FENCE_ASYNC_SHARED() asm volatile("fence.proxy.async.shared::cta;" ::: "memory")

#define TC_LD_X32(r, addr) \
    asm volatile("tcgen05.ld.sync.aligned.32x32b.x32.b32 " \
        "{%0, %1, %2, %3, %4, %5, %6, %7, " \
        " %8, %9, %10, %11, %12, %13, %14, %15, " \
        " %16, %17, %18, %19, %20, %21, %22, %23, " \
        " %24, %25, %26, %27, %28, %29, %30, %31}, [%32];" \
        : "=r"((r)[0]),  "=r"((r)[1]),  "=r"((r)[2]),  "=r"((r)[3]), \
          "=r"((r)[4]),  "=r"((r)[5]),  "=r"((r)[6]),  "=r"((r)[7]), \
          "=r"((r)[8]),  "=r"((r)[9]),  "=r"((r)[10]), "=r"((r)[11]), \
          "=r"((r)[12]), "=r"((r)[13]), "=r"((r)[14]), "=r"((r)[15]), \
          "=r"((r)[16]), "=r"((r)[17]), "=r"((r)[18]), "=r"((r)[19]), \
          "=r"((r)[20]), "=r"((r)[21]), "=r"((r)[22]), "=r"((r)[23]), \
          "=r"((r)[24]), "=r"((r)[25]), "=r"((r)[26]), "=r"((r)[27]), \
          "=r"((r)[28]), "=r"((r)[29]), "=r"((r)[30]), "=r"((r)[31]) \
        : "r"(addr))

__device__ __forceinline__ void mma_tf32(uint32_t d, uint64_t a, uint64_t b,
                                         uint32_t idesc, uint32_t acc) {
    asm volatile("{\n\t.reg .pred p;\n\tsetp.ne.u32 p, %5, 0;\n\t"
                 "tcgen05.mma.cta_group::1.kind::tf32 [%0], %1, %2, %3, {%4, %4, %4, %4}, p;\n\t}"
                 :: "r"(d), "l"(a), "l"(b), "r"(idesc), "r"(0u), "r"(acc) : "memory");
}

// Load a 128x64 fp32 tile, split to tf32 hi/lo, store swizzled.
__device__ __forceinline__ void load_qk_tile(const float* __restrict__ g, char* sm,
                                             uint32_t hi_off, uint32_t lo_off,
                                             float scale, int t) {
#pragma unroll
    for (int rr = 0; rr < 2; rr++) {
        int row = rr * 64 + (t >> 2);
        int c0 = (t & 3) * 16;
        const float* src = g + (size_t)row * (Hh * Dd) + c0;
#pragma unroll
        for (int c4 = 0; c4 < 4; c4++) {
            float4 v = *(const float4*)(src + c4 * 4);
            float x[4] = {v.x * scale, v.y * scale, v.z * scale, v.w * scale};
            float4 hi4, lo4;
            float* ph = &hi4.x;
            float* pl = &lo4.x;
#pragma unroll
            for (int j = 0; j < 4; j++) {
                uint32_t hb;
                asm("cvt.rna.tf32.f32 %0, %1;" : "=r"(hb) : "f"(x[j]));
                float h = __uint_as_float(hb);
                ph[j] = h;
                pl[j] = x[j] - h;
            }
            uint32_t o = off128(row, c0 + c4 * 4);
            *(float4*)(sm + hi_off + o) = hi4;
            *(float4*)(sm + lo_off + o) = lo4;
        }
    }
}

// Load a 128x64 V tile, store TRANSPOSED (V^T: 64 rows x 128 cols) swizzled.
__device__ __forceinline__ void load_v_tile(const float* __restrict__ g, char* sm, int t) {
#pragma unroll
    for (int rr = 0; rr < 2; rr++) {
        int n = rr * 64 + (t >> 2);
        int d0 = (t & 3) * 16;
        const float* src = g + (size_t)n * (Hh * Dd) + d0;
#pragma unroll
        for (int c4 = 0; c4 < 4; c4++) {
            float4 v = *(const float4*)(src + c4 * 4);
            int d = d0 + c4 * 4;
            *(float*)(sm + OFF_VT + off64(d + 0, n)) = v.x;
            *(float*)(sm + OFF_VT + off64(d + 1, n)) = v.y;
            *(float*)(sm + OFF_VT + off64(d + 2, n)) = v.z;
            *(float*)(sm + OFF_VT + off64(d + 3, n)) = v.w;
        }
    }
}
#endif  // USE_TC

__global__ __launch_bounds__(256, 1) __cluster_dims__(1, 1, 1)
void attn_pass1_tc(const float* __restrict__ q, const float* __restrict__ k,
                   const float* __restrict__ v, float* __restrict__ out,
                   float* __restrict__ attn) {
    extern __shared__ char sm[];
    const int t = threadIdx.x;
    const int w = t >> 5, lid = t & 31;
    const int bh = blockIdx.y, b = bh >> 4, h = bh & 15;
    const int qt = (NQT - 1) - blockIdx.x;  // big tiles first
    const int qr0 = qt * TM;

    const float* qb = q + (size_t)b * Ss * Hh * Dd + (size_t)h * Dd;
    const float* kb = k + (size_t)b * Ss * Hh * Dd + (size_t)h * Dd;
    const float* vb = v + (size_t)b * Ss * Hh * Dd + (size_t)h * Dd;
    float* attnb = attn + (size_t)bh * Ss * Ss;

#if USE_TC
    // =========================== tcgen05 path ===========================
    const uint32_t sb = smem_u32(sm);

    if (w == 0) TC_ALLOC(sb + SMEM_TMEMPTR, 256);
    if (t == 0) {
        MBAR_INIT(sb + SMEM_MBAR_S, 1);
        MBAR_INIT(sb + SMEM_MBAR_PV, 1);
    }
    load_qk_tile(qb + (size_t)qr0 * (Hh * Dd), sm, OFF_QHI, OFF_QLO, 0.125f, t);
    FENCE_ASYNC_SHARED();
    __syncthreads();

    uint32_t tmem;
    asm volatile("ld.shared.b32 %0, [%1];" : "=r"(tmem) : "r"(sb + SMEM_TMEMPTR));
    const uint32_t S_T = tmem;        // S: cols 0..127
    const uint32_t O_T = tmem + 128;  // out: cols 128..191

    const uint64_t dq_hi = MAKE_DESC(sb + OFF_QHI);
    const uint64_t dq_lo = MAKE_DESC(sb + OFF_QLO);
    const uint64_t dk_hi = MAKE_DESC(sb + OFF_KHI);
    const uint64_t dk_lo = MAKE_DESC(sb + OFF_KLO);
    const uint64_t dps   = MAKE_DESC(sb + OFF_PS);
    const uint64_t dvt   = MAKE_DESC(sb + OFF_VT);

    const int sp = w & 3;
    const int ch = (w >> 2) * 64;
    const int m = sp * 32 + lid;
    const int rowg = qr0 + m;
    float lsum = 0.f;
    int s_ph = 0, pv_ph = 0;

    for (int kt = 0; kt <= qt; kt++) {
        const int kc0 = kt * TN;
        if (kt > 0) { MBAR_WAIT(sb + SMEM_MBAR_PV, pv_ph); pv_ph ^= 1; }

        load_qk_tile(kb + (size_t)kc0 * (Hh * Dd), sm, OFF_KHI, OFF_KLO, 1.0f, t);
        load_v_tile(vb + (size_t)kc0 * (Hh * Dd), sm, t);
        FENCE_ASYNC_SHARED();
        __syncthreads();

        // S = Qhi*Khi + Qhi*Klo + Qlo*Khi  (split tf32 ~ fp32)
        if (w == 0 && elect_one()) {
#pragma unroll
            for (int kc = 0; kc < 8; kc++) {
                uint64_t o = (uint64_t)(((kc >> 2) << 10) + ((kc & 3) << 1));
                mma_tf32(S_T, dq_hi + o, dk_hi + o, IDESC_S, kc > 0);
                mma_tf32(S_T, dq_hi + o, dk_lo + o, IDESC_S, 1);
                mma_tf32(S_T, dq_lo + o, dk_hi + o, IDESC_S, 1);
            }
            TC_COMMIT(sb + SMEM_MBAR_S);
        }
        MBAR_WAIT(sb + SMEM_MBAR_S, s_ph);
        s_ph ^= 1;
        TC_FENCE_AFTER();

        const bool diag = (kt == qt);
#pragma unroll
        for (int half = 0; half < 2; half++) {
            uint32_t r[32];
            TC_LD_X32(r, S_T + ch + half * 32);
            TC_WAIT_LD();
            const int cl0 = ch + half * 32;
#pragma unroll
            for (int j = 0; j < 32; j += 4) {
                float4 pv4;
                float* pp = &pv4.x;
#pragma unroll
                for (int jj = 0; jj < 4; jj++) {
                    float e = __expf(__uint_as_float(r[j + jj]));
                    if (diag && (kc0 + cl0 + j + jj > rowg)) e = 0.f;
                    pp[jj] = e;
                    lsum += e;
                }
                *(float4*)(sm + OFF_PS + off128(m, cl0 + j)) = pv4;
            }
        }
        TC_FENCE_BEFORE();
        FENCE_ASYNC_SHARED();
        __syncthreads();

        // out += P * V^T
        if (w == 0 && elect_one()) {
#pragma unroll
            for (int kc = 0; kc < 16; kc++) {
                uint64_t oa = (uint64_t)(((kc >> 2) << 10) + ((kc & 3) << 1));
                uint64_t ob = (uint64_t)(((kc >> 2) << 9) + ((kc & 3) << 1));
                mma_tf32(O_T, dps + oa, dvt + ob, IDESC_O, !(kt == 0 && kc == 0));
            }
            TC_COMMIT(sb + SMEM_MBAR_PV);
        }

        // coalesced store of unnormalized P (overlaps PV MMA)
#pragma unroll
        for (int it = 0; it < 16; it++) {
            int e = (it * 256 + t) * 4;
            int row = e >> 7, col = e & 127;
            float4 val = *(const float4*)(sm + OFF_PS + off128(row, col));
            *(float4*)&attnb[(size_t)(qr0 + row) * Ss + kc0 + col] = val;
        }
    }

    // zero-fill masked (strictly upper) region
    {
        const int zc0 = (qt + 1) * TN;
        const float4 z = make_float4(0.f, 0.f, 0.f, 0.f);
        for (int rr = w; rr < TM; rr += 8) {
            float* rowp = attnb + (size_t)(qr0 + rr) * Ss;
            for (int c = zc0 + lid * 4; c < Ss; c += 128)
                *(float4*)(rowp + c) = z;
        }
    }

    ((float*)(sm + SMEM_RS))[(w >> 2) * 128 + m] = lsum;
    __syncthreads();

    MBAR_WAIT(sb + SMEM_MBAR_PV, pv_ph);
    TC_FENCE_AFTER();
    {
        float tot = ((float*)(sm + SMEM_RS))[m] + ((float*)(sm + SMEM_RS))[128 + m];
        float inv = 1.0f / tot;
        if (w < 4) g_linv[bh * Ss + qr0 + m] = inv;
        uint32_t r[32];
        TC_LD_X32(r, O_T + (w >> 2) * 32);
        TC_WAIT_LD();
        TC_FENCE_BEFORE();
        float* op = out + (size_t)b * Ss * Hh * Dd + (size_t)(qr0 + m) * (Hh * Dd) +
                    h * Dd + (w >> 2) * 32;
#pragma unroll
        for (int j = 0; j < 32; j += 4) {
            float4 o4 = make_float4(__uint_as_float(r[j]) * inv,
                                    __uint_as_float(r[j + 1]) * inv,
                                    __uint_as_float(r[j + 2]) * inv,
                                    __uint_as_float(r[j + 3]) * inv);
            *(float4*)(op + j) = o4;
        }
    }
    __syncthreads();
    if (t == 0) { MBAR_INVAL(sb + SMEM_MBAR_S); MBAR_INVAL(sb + SMEM_MBAR_PV); }
    __syncthreads();
    if (w == 0) {
        TC_RELINQ();
        TC_DEALLOC(tmem, 256);
    }
#else
    // =========================== FFMA fallback ===========================
    float* q_t = (float*)sm;                  // [64][132] transposed, scaled
    float* k_t = (float*)(sm + 33792);        // [64][132] transposed
    float* v_s = (float*)(sm + 67584);        // [128][68]
    float* p_s = (float*)(sm + 102400);       // [128][132]

    const int ty = t >> 4, tx = t & 15;

    // load Q transposed + scaled
    {
#pragma unroll
        for (int rr = 0; rr < 2; rr++) {
            int row = rr * 64 + (t >> 2);
            int c0 = (t & 3) * 16;
            const float* src = qb + (size_t)(qr0 + row) * (Hh * Dd) + c0;
#pragma unroll
            for (int c4 = 0; c4 < 4; c4++) {
                float4 val = *(const float4*)(src + c4 * 4);
                int d = c0 + c4 * 4;
                q_t[(d + 0) * 132 + row] = val.x * 0.125f;
                q_t[(d + 1) * 132 + row] = val.y * 0.125f;
                q_t[(d + 2) * 132 + row] = val.z * 0.125f;
                q_t[(d + 3) * 132 + row] = val.w * 0.125f;
            }
        }
    }
    __syncthreads();

    float acc_o[8][4];
#pragma unroll
    for (int i = 0; i < 8; i++)
#pragma unroll
        for (int j = 0; j < 4; j++) acc_o[i][j] = 0.f;
    float lsum[8] = {0.f, 0.f, 0.f, 0.f, 0.f, 0.f, 0.f, 0.f};

    for (int kt = 0; kt <= qt; kt++) {
        const int kc0 = kt * TN;
        // load K transposed
#pragma unroll
        for (int rr = 0; rr < 2; rr++) {
            int row = rr * 64 + (t >> 2);
            int c0 = (t & 3) * 16;
            const float* src = kb + (size_t)(kc0 + row) * (Hh * Dd) + c0;
#pragma unroll
            for (int c4 = 0; c4 < 4; c4++) {
                float4 val = *(const float4*)(src + c4 * 4);
                int d = c0 + c4 * 4;
                k_t[(d + 0) * 132 + row] = val.x;
                k_t[(d + 1) * 132 + row] = val.y;
                k_t[(d + 2) * 132 + row] = val.z;
                k_t[(d + 3) * 132 + row] = val.w;
            }
        }
        // load V
        {
            int row = t >> 1;
            int c0 = (t & 1) * 32;
            const float* src = vb + (size_t)(kc0 + row) * (Hh * Dd) + c0;
#pragma unroll
            for (int c4 = 0; c4 < 8; c4++)
                *(float4*)&v_s[row * 68 + c0 + c4 * 4] = *(const float4*)(src + c4 * 4);
        }
        __syncthreads();

        // S = Q K^T  (8x8 microtile)
        float s_[8][8];
#pragma unroll
        for (int i = 0; i < 8; i++)
#pragma unroll
            for (int j = 0; j < 8; j++) s_[i][j] = 0.f;
#pragma unroll 2
        for (int d = 0; d < 64; d++) {
            float a[8], bv[8];
            *(float4*)&a[0] = *(const float4*)&q_t[d * 132 + 8 * ty];
            *(float4*)&a[4] = *(const float4*)&q_t[d * 132 + 8 * ty + 4];
            *(float4*)&bv[0] = *(const float4*)&k_t[d * 132 + 8 * tx];
            *(float4*)&bv[4] = *(const float4*)&k_t[d * 132 + 8 * tx + 4];
#pragma unroll
            for (int i = 0; i < 8; i++)
#pragma unroll
                for (int j = 0; j < 8; j++) s_[i][j] += a[i] * bv[j];
        }

        // exp + mask, write P to smem & gmem
#pragma unroll
        for (int i = 0; i < 8; i++) {
            const int rg = qr0 + 8 * ty + i;
            float p[8];
#pragma unroll
            for (int j = 0; j < 8; j++) {
                const int cg = kc0 + 8 * tx + j;
                float e = (cg <= rg) ? __expf(s_[i][j]) : 0.f;
                p[j] = e;
                lsum[i] += e;
            }
            *(float4*)&p_s[(8 * ty + i) * 132 + 8 * tx] = *(float4*)&p[0];
            *(float4*)&p_s[(8 * ty + i) * 132 + 8 * tx + 4] = *(float4*)&p[4];
            float* gp = &attnb[(size_t)rg * Ss + kc0 + 8 * tx];
            *(float4*)gp = *(float4*)&p[0];
            *(float4*)(gp + 4) = *(float4*)&p[4];
        }
        __syncthreads();

        // O += P V   (8 rows x 4 cols per thread)
#pragma unroll 2
        for (int n = 0; n < 128; n++) {
            float4 vv = *(const float4*)&v_s[n * 68 + 4 * tx];
#pragma unroll
            for (int i = 0; i < 8; i++) {
                float pv = p_s[(8 * ty + i) * 132 + n];
                acc_o[i][0] += pv * vv.x;
                acc_o[i][1] += pv * vv.y;
                acc_o[i][2] += pv * vv.z;
                acc_o[i][3] += pv * vv.w;
            }
        }
        __syncthreads();
    }

    // zero-fill masked region
    {
        const int zc0 = (qt + 1) * TN;
        const float4 z = make_float4(0.f, 0.f, 0.f, 0.f);
        for (int rr = w; rr < TM; rr += 8) {
            float* rowp = attnb + (size_t)(qr0 + rr) * Ss;
            for (int c = zc0 + lid * 4; c < Ss; c += 128)
                *(float4*)(rowp + c) = z;
        }
    }

    // reduce row sums over tx lanes
    float inv[8];
#pragma unroll
    for (int i = 0; i < 8; i++) {
        float s = lsum[i];
        s += __shfl_xor_sync(0xffffffffu, s, 1);
        s += __shfl_xor_sync(0xffffffffu, s, 2);
        s += __shfl_xor_sync(0xffffffffu, s, 4);
        s += __shfl_xor_sync(0xffffffffu, s, 8);
        inv[i] = 1.0f / s;
    }
    if (tx == 0) {
#pragma unroll
        for (int i = 0; i < 8; i++)
            g_linv[bh * Ss + qr0 + 8 * ty + i] = inv[i];
    }
#pragma unroll
    for (int i = 0; i < 8; i++) {
        const int rg = qr0 + 8 * ty + i;
        float4 o4 = make_float4(acc_o[i][0] * inv[i], acc_o[i][1] * inv[i],
                                acc_o[i][2] * inv[i], acc_o[i][3] * inv[i]);
        *(float4*)&out[(size_t)b * Ss * Hh * Dd + (size_t)rg * (Hh * Dd) + h * Dd + 4 * tx] = o4;
    }
#endif
}

// Normalize the causal prefix. Pair row j with row 2047-j for load balance.
__global__ __launch_bounds__(256) void attn_norm2(float* __restrict__ attn) {
    const int x = blockIdx.x;
    const int bh = x >> 10;
    const int jl = x & 1023;
    float* base = attn + (size_t)bh * Ss * Ss;
#pragma unroll
    for (int which = 0; which < 2; which++) {
        const int row = which ? (Ss - 1 - jl) : jl;
        const float inv = g_linv[bh * Ss + row];
        const int n4 = (row + 4) >> 2;
        float4* p = (float4*)(base + (size_t)row * Ss);
        for (int c = threadIdx.x; c < n4; c += 256) {
            float4 u = p[c];
            u.x *= inv; u.y *= inv; u.z *= inv; u.w *= inv;
            p[c] = u;
        }
    }
}

extern "C" void kernel_launch(void* const* d_in, const int* in_sizes, int n_in,
                              void* d_out, int out_size) {
    const float* q = (const float*)d_in[0];
    const float* k = (const float*)d_in[1];
    const float* v = (const float*)d_in[2];
    // d_in[3] = causal mask (deterministic triu) -> handled analytically

    float* out = (float*)d_out;
    float* attn = (float*)d_out + (size_t)Bb * Ss * Hh * Dd;

    cudaFuncSetAttribute(attn_pass1_tc, cudaFuncAttributeMaxDynamicSharedMemorySize,
                         SMEM_BYTES);

    dim3 grid(NQT, BHh);
    attn_pass1_tc<<<grid, 256, SMEM_BYTES>>>(q, k, v, out, attn);
    attn_norm2<<<BHh * 1024, 256>>>(attn);
}